// round 15
// baseline (speedup 1.0000x reference)
#include <cuda_runtime.h>
#include <cuda_fp16.h>
#include <math.h>
#include <cstdint>

// ---------------- problem constants ----------------
#define BSZ     2
#define SEQLEN  2048
#define DIM     2048
#define NH      16
#define NKV     4
#define HD      128
#define QKV_OUT 3072
#define TOKENS  (BSZ*SEQLEN)
#define REPARAM_EPS 1e-6f
#define L2_EPS      1e-12f

// ---------------- device scratch ----------------
__device__ __half g_xh   [TOKENS * DIM];
__device__ __half g_wqh  [QKV_OUT * DIM];
__device__ __half g_woh  [DIM * DIM];
__device__ __half g_qh   [TOKENS * NH  * HD];
__device__ __half g_kh   [TOKENS * NKV * HD];
__device__ __half g_vh   [TOKENS * NKV * HD];
__device__ __half g_attnh[TOKENS * DIM];

// ---------------- helpers ----------------
__device__ __forceinline__ void mma16(float* c, const unsigned* a, unsigned b0, unsigned b1) {
    asm volatile(
        "mma.sync.aligned.m16n8k16.row.col.f32.f16.f16.f32 "
        "{%0,%1,%2,%3},{%4,%5,%6,%7},{%8,%9},{%0,%1,%2,%3};"
        : "+f"(c[0]), "+f"(c[1]), "+f"(c[2]), "+f"(c[3])
        : "r"(a[0]), "r"(a[1]), "r"(a[2]), "r"(a[3]), "r"(b0), "r"(b1));
}
__device__ __forceinline__ unsigned smem_u32(const void* p) {
    return (unsigned)__cvta_generic_to_shared(p);
}
__device__ __forceinline__ void cp16(unsigned dst, const void* src) {
    asm volatile("cp.async.cg.shared.global [%0], [%1], 16;" :: "r"(dst), "l"(src));
}
#define CP_COMMIT() asm volatile("cp.async.commit_group;")
#define CP_WAIT(n)  asm volatile("cp.async.wait_group %0;" :: "n"(n))
#define LDSM4(r, addr) \
    asm volatile("ldmatrix.sync.aligned.m8n8.x4.shared.b16 {%0,%1,%2,%3},[%4];" \
        : "=r"((r)[0]), "=r"((r)[1]), "=r"((r)[2]), "=r"((r)[3]) : "r"(addr))
#define LDSM4T(r, addr) \
    asm volatile("ldmatrix.sync.aligned.m8n8.x4.trans.shared.b16 {%0,%1,%2,%3},[%4];" \
        : "=r"((r)[0]), "=r"((r)[1]), "=r"((r)[2]), "=r"((r)[3]) : "r"(addr))
__device__ __forceinline__ unsigned packh2(float x, float y) {
    __half2 h = __floats2half2_rn(x, y);
    return *(unsigned*)&h;
}
__device__ __forceinline__ float ex2f(float x) {
    float r;
    asm("ex2.approx.ftz.f32 %0, %1;" : "=f"(r) : "f"(x));
    return r;
}

// ---------------- combined prep: f2h(x) + rownorm(qkv_w) + rownorm(out_w) ---
__device__ __forceinline__ void wnorm_row(const float* __restrict__ row,
                                          __half* __restrict__ orow) {
    int c = threadIdx.x * 8;
    float4 v0 = *(const float4*)(row + c);
    float4 v1 = *(const float4*)(row + c + 4);
    float ss = v0.x*v0.x + v0.y*v0.y + v0.z*v0.z + v0.w*v0.w
             + v1.x*v1.x + v1.y*v1.y + v1.z*v1.z + v1.w*v1.w;
    #pragma unroll
    for (int off = 16; off; off >>= 1) ss += __shfl_xor_sync(0xffffffffu, ss, off);
    __shared__ float sp[8];
    if ((threadIdx.x & 31) == 0) sp[threadIdx.x >> 5] = ss;
    __syncthreads();
    __shared__ float s_inv;
    if (threadIdx.x == 0) {
        float tot = 0.f;
        #pragma unroll
        for (int i = 0; i < 8; i++) tot += sp[i];
        s_inv = 1.f / (sqrtf(tot) + REPARAM_EPS);
    }
    __syncthreads();
    float inv = s_inv;
    uint4 u;
    u.x = packh2(v0.x * inv, v0.y * inv);
    u.y = packh2(v0.z * inv, v0.w * inv);
    u.z = packh2(v1.x * inv, v1.y * inv);
    u.w = packh2(v1.z * inv, v1.w * inv);
    *(uint4*)&orow[c] = u;
}

__global__ void prep_kernel(const float* __restrict__ x, __half* __restrict__ xh,
                            const float* __restrict__ qkv_w, __half* __restrict__ wqh,
                            const float* __restrict__ out_w, __half* __restrict__ woh) {
    int bid = blockIdx.x;
    if (bid < 4096) {
        int i = (bid * 256 + threadIdx.x) * 8;
        float4 a = *(const float4*)(x + i);
        float4 b = *(const float4*)(x + i + 4);
        uint4 u;
        u.x = packh2(a.x, a.y); u.y = packh2(a.z, a.w);
        u.z = packh2(b.x, b.y); u.w = packh2(b.z, b.w);
        *(uint4*)&xh[i] = u;
    } else if (bid < 4096 + QKV_OUT) {
        int r = bid - 4096;
        wnorm_row(qkv_w + (size_t)r * DIM, wqh + (size_t)r * DIM);
    } else {
        int r = bid - 4096 - QKV_OUT;
        wnorm_row(out_w + (size_t)r * DIM, woh + (size_t)r * DIM);
    }
}

// ---------------- shared GEMM mainloop: 2-stage, static offsets -------------
// SAFE ordering: wait -> sync -> compute(s) -> sync -> issue into s.
#define GBK    64
#define GSTRH  72
#define GSTAGE (128 * GSTRH)
#define GEMM_SMEM (2 * 2 * GSTAGE * 2)     // 73728 bytes

#define GEMM_COMPUTE(SOFF)                                                     \
    {                                                                          \
        unsigned aoff = aBase + (SOFF);                                        \
        unsigned boff = bBase + (SOFF);                                        \
        _Pragma("unroll")                                                      \
        for (int ks = 0; ks < 4; ks++) {                                       \
            unsigned a0[4], a1[4];                                             \
            LDSM4(a0, aoff + ks * 32);                                         \
            LDSM4(a1, aoff + ks * 32 + 16 * GSTRH * 2);                        \
            _Pragma("unroll")                                                  \
            for (int p = 0; p < 4; p++) {                                      \
                unsigned bb[4];                                                \
                LDSM4(bb, boff + ks * 32 + p * 16 * GSTRH * 2);                \
                mma16(acc[0][2*p],   a0, bb[0], bb[1]);                        \
                mma16(acc[0][2*p+1], a0, bb[2], bb[3]);                        \
                mma16(acc[1][2*p],   a1, bb[0], bb[1]);                        \
                mma16(acc[1][2*p+1], a1, bb[2], bb[3]);                        \
            }                                                                  \
        }                                                                      \
    }

#define GEMM_MAINLOOP(A_, B_, K_)                                              \
    extern __shared__ char smraw[];                                            \
    __half* As = (__half*)smraw;                                               \
    __half* Bs = As + 2 * GSTAGE;                                              \
    unsigned asb = smem_u32(As), bsb = smem_u32(Bs);                           \
    int tid = threadIdx.x, lane = tid & 31, wid = tid >> 5;                    \
    int wm = wid & 3, wn = wid >> 2, g = lane >> 2, t = lane & 3;              \
    int bm = blockIdx.y * 128, bn = blockIdx.x * 128;                          \
    int aRow = wm * 32 + ((lane >> 3) & 1) * 8 + (lane & 7);                   \
    int aK   = ((lane >> 4) & 1) * 8;                                          \
    int bRow = wn * 64 + ((lane >> 4) & 1) * 8 + (lane & 7);                   \
    int bK   = ((lane >> 3) & 1) * 8;                                          \
    unsigned aBase = asb + (aRow * GSTRH + aK) * 2;                            \
    unsigned bBase = bsb + (bRow * GSTRH + bK) * 2;                            \
    float acc[2][8][4];                                                        \
    _Pragma("unroll")                                                          \
    for (int mt = 0; mt < 2; mt++)                                             \
        _Pragma("unroll")                                                      \
        for (int nt = 0; nt < 8; nt++)                                         \
            _Pragma("unroll")                                                  \
            for (int i = 0; i < 4; i++) acc[mt][nt][i] = 0.f;                  \
    auto issue = [&](int kb, int s) {                                          \
        int k0 = kb * GBK;                                                     \
        _Pragma("unroll")                                                      \
        for (int i = 0; i < 4; i++) {                                          \
            int idx = tid + i * 256;                                           \
            int r = idx >> 3, c = idx & 7;                                     \
            cp16(asb + (s * GSTAGE + r * GSTRH + c * 8) * 2,                   \
                 (A_) + (size_t)(bm + r) * (K_) + k0 + c * 8);                 \
            cp16(bsb + (s * GSTAGE + r * GSTRH + c * 8) * 2,                   \
                 (B_) + (size_t)(bn + r) * (K_) + k0 + c * 8);                 \
        }                                                                      \
        CP_COMMIT();                                                           \
    };                                                                         \
    int NIT = (K_) / GBK;   /* even */                                         \
    issue(0, 0);                                                               \
    issue(1, 1);                                                               \
    for (int kb = 0; kb < NIT; kb += 2) {                                      \
        CP_WAIT(1);                                                            \
        __syncthreads();                                                       \
        GEMM_COMPUTE(0)                                                        \
        __syncthreads();                                                       \
        if (kb + 2 < NIT) issue(kb + 2, 0); else CP_COMMIT();                  \
        CP_WAIT(1);                                                            \
        __syncthreads();                                                       \
        GEMM_COMPUTE(GSTAGE * 2)                                               \
        __syncthreads();                                                       \
        if (kb + 3 < NIT) issue(kb + 3, 1); else CP_COMMIT();                  \
    }

// ---------------- GEMM1: QKV projection with FUSED rope/l2norm epilogue -----
__global__ __launch_bounds__(256, 2) void gemm_qkv(const __half* __restrict__ A,
                                                   const __half* __restrict__ B,
                                                   const float* __restrict__ fc,
                                                   const float* __restrict__ fs,
                                                   const float* __restrict__ s_q,
                                                   const float* __restrict__ s_k,
                                                   __half* __restrict__ qo,
                                                   __half* __restrict__ ko,
                                                   __half* __restrict__ vo) {
    GEMM_MAINLOOP(A, B, DIM)

    int h = blockIdx.x;
    int row0 = bm + wm * 32 + g;

    if (h >= 20) {
        __half* dst = vo + (h - 20) * HD;
        #pragma unroll
        for (int mt = 0; mt < 2; mt++) {
            size_t r0 = (size_t)(row0 + mt * 16) * (NKV * HD);
            size_t r1 = r0 + (size_t)8 * (NKV * HD);
            #pragma unroll
            for (int nt = 0; nt < 8; nt++) {
                int d = wn * 64 + nt * 8 + 2 * t;
                *(__half2*)&dst[r0 + d] = __floats2half2_rn(acc[mt][nt][0], acc[mt][nt][1]);
                *(__half2*)&dst[r1 + d] = __floats2half2_rn(acc[mt][nt][2], acc[mt][nt][3]);
            }
        }
        return;
    }

    __syncthreads();
    float* ssred = (float*)smraw;          // [2][128]

    float ss[2][2] = {{0.f, 0.f}, {0.f, 0.f}};
    #pragma unroll
    for (int mt = 0; mt < 2; mt++) {
        int s0 = (row0 + mt * 16) & (SEQLEN - 1);
        int s1 = (row0 + mt * 16 + 8) & (SEQLEN - 1);
        #pragma unroll
        for (int nt = 0; nt < 8; nt++) {
            int i = wn * 32 + nt * 4 + t;
            float c0 = fc[s0 * 64 + i], sn0 = fs[s0 * 64 + i];
            float c1 = fc[s1 * 64 + i], sn1 = fs[s1 * 64 + i];
            float xr0 = acc[mt][nt][0], xi0 = acc[mt][nt][1];
            float xr1 = acc[mt][nt][2], xi1 = acc[mt][nt][3];
            float or0 = xr0 * c0 - xi0 * sn0, oi0 = xr0 * sn0 + xi0 * c0;
            float or1 = xr1 * c1 - xi1 * sn1, oi1 = xr1 * sn1 + xi1 * c1;
            acc[mt][nt][0] = or0; acc[mt][nt][1] = oi0;
            acc[mt][nt][2] = or1; acc[mt][nt][3] = oi1;
            ss[mt][0] += or0 * or0 + oi0 * oi0;
            ss[mt][1] += or1 * or1 + oi1 * oi1;
        }
        ss[mt][0] += __shfl_xor_sync(0xffffffffu, ss[mt][0], 1);
        ss[mt][0] += __shfl_xor_sync(0xffffffffu, ss[mt][0], 2);
        ss[mt][1] += __shfl_xor_sync(0xffffffffu, ss[mt][1], 1);
        ss[mt][1] += __shfl_xor_sync(0xffffffffu, ss[mt][1], 2);
    }
    int lr0 = wm * 32 + g;
    if (t == 0) {
        ssred[wn * 128 + lr0]      = ss[0][0];
        ssred[wn * 128 + lr0 + 8]  = ss[0][1];
        ssred[wn * 128 + lr0 + 16] = ss[1][0];
        ssred[wn * 128 + lr0 + 24] = ss[1][1];
    }
    __syncthreads();

    const float* sc = (h < NH) ? s_q : s_k;
    __half* dst = (h < NH) ? (qo + h * HD) : (ko + (h - NH) * HD);
    int ldo = (h < NH) ? (NH * HD) : (NKV * HD);

    #pragma unroll
    for (int mt = 0; mt < 2; mt++) {
        float inv0 = 1.f / (sqrtf(ssred[lr0 + mt*16]     + ssred[128 + lr0 + mt*16])     + L2_EPS);
        float inv1 = 1.f / (sqrtf(ssred[lr0 + mt*16 + 8] + ssred[128 + lr0 + mt*16 + 8]) + L2_EPS);
        size_t r0 = (size_t)(row0 + mt * 16) * ldo;
        size_t r1 = r0 + (size_t)8 * ldo;
        #pragma unroll
        for (int nt = 0; nt < 8; nt++) {
            int d = wn * 64 + nt * 8 + 2 * t;
            float2 scv = *(const float2*)&sc[d];
            *(__half2*)&dst[r0 + d] = __floats2half2_rn(acc[mt][nt][0] * inv0 * scv.x,
                                                        acc[mt][nt][1] * inv0 * scv.y);
            *(__half2*)&dst[r1 + d] = __floats2half2_rn(acc[mt][nt][2] * inv1 * scv.x,
                                                        acc[mt][nt][3] * inv1 * scv.y);
        }
    }
}

// ---------------- GEMM2: out projection (fp32 output) ----------------------
__global__ __launch_bounds__(256, 2) void gemm_fp16(const __half* __restrict__ A,
                                                    const __half* __restrict__ B,
                                                    float* __restrict__ C,
                                                    int M, int N, int K) {
    GEMM_MAINLOOP(A, B, K)
    #pragma unroll
    for (int mt = 0; mt < 2; mt++) {
        int r0 = bm + wm * 32 + mt * 16 + g;
        #pragma unroll
        for (int nt = 0; nt < 8; nt++) {
            int c = bn + wn * 64 + nt * 8 + 2 * t;
            *(float2*)&C[(size_t)r0 * N + c]       = make_float2(acc[mt][nt][0], acc[mt][nt][1]);
            *(float2*)&C[(size_t)(r0 + 8) * N + c] = make_float2(acc[mt][nt][2], acc[mt][nt][3]);
        }
    }
}

// ---------------- flash attention: 4 warps x 32 q-rows, static-max ----------
// l on tensor cores (ones-column). Bias row in smem. Static-stage unroll x2.
// (compute -> sync -> issue ordering: verified safe)
#define KVSTR 136
#define KVST  (64 * KVSTR)
#define FSMEM (((128 * KVSTR + 2 * 2 * KVST) * 2) + SEQLEN * 4)  // 112640 bytes
#define SCL2  16.322447f     // sqrt(128)*log2(e)
#define MAX2  8.0f
#define ONESH 0x3C003C00u    // half2(1,1)

__global__ __launch_bounds__(128, 2) void flash_fp16(const __half* __restrict__ Qh,
                                                     const __half* __restrict__ Kh,
                                                     const __half* __restrict__ Vh,
                                                     const int* __restrict__ mask,
                                                     __half* __restrict__ Oh) {
    extern __shared__ char smraw[];
    __half* Qs  = (__half*)smraw;
    __half* Ksm = Qs + 128 * KVSTR;
    __half* Vsm = Ksm + 2 * KVST;
    float* Bias = (float*)(Vsm + 2 * KVST);
    unsigned qsb = smem_u32(Qs), ksb = smem_u32(Ksm), vsb = smem_u32(Vsm);

    int tid = threadIdx.x, lane = tid & 31, wid = tid >> 5;
    int g = lane >> 2, t = lane & 3;
    int qb = blockIdx.x, h = blockIdx.y, b = blockIdx.z, hk = h >> 2;
    int q0 = qb * 128, qrow0 = wid * 32;
    const unsigned KVSTAGE = KVST * 2;

    auto issue_kv = [&](int kb, int s) {
        int k0 = kb * 64;
        #pragma unroll
        for (int i = 0; i < 8; i++) {
            int idx = tid + i * 128;
            int r = idx >> 4, c = idx & 15;
            size_t tok = (size_t)(b * SEQLEN + k0 + r);
            cp16(ksb + s * KVSTAGE + (r * KVSTR + c * 8) * 2,
                 Kh + (tok * NKV + hk) * HD + c * 8);
            cp16(vsb + s * KVSTAGE + (r * KVSTR + c * 8) * 2,
                 Vh + (tok * NKV + hk) * HD + c * 8);
        }
        CP_COMMIT();
    };

    #pragma unroll
    for (int i = 0; i < 16; i++) {
        int idx = tid + i * 128;
        int r = idx >> 4, c = idx & 15;
        cp16(qsb + (r * KVSTR + c * 8) * 2,
             Qh + ((size_t)(b * SEQLEN + q0 + r) * NH + h) * HD + c * 8);
    }
    CP_COMMIT();
    issue_kv(0, 0);
    issue_kv(1, 1);

    for (int i = tid; i < SEQLEN; i += 128)
        Bias[i] = mask[b * SEQLEN + i] ? -MAX2 : -1e30f;

    float o[2][16][4];
    #pragma unroll
    for (int mt = 0; mt < 2; mt++)
        #pragma unroll
        for (int nt = 0; nt < 16; nt++)
            #pragma unroll
            for (int i = 0; i < 4; i++) o[mt][nt][i] = 0.f;
    float lc[2][4];
    #pragma unroll
    for (int mt = 0; mt < 2; mt++)
        #pragma unroll
        for (int i = 0; i < 4; i++) lc[mt][i] = 0.f;

    int qr  = ((lane >> 3) & 1) * 8 + (lane & 7);
    int qk  = ((lane >> 4) & 1) * 8;
    int kRow = ((lane >> 4) & 1) * 8 + (lane & 7);
    int kK   = ((lane >> 3) & 1) * 8;
    int vRow = lane & 15;
    int vD   = ((lane >> 4) & 1) * 8;
    unsigned qBase0 = qsb + ((qrow0 + qr) * KVSTR + qk) * 2;
    unsigned qBase1 = qsb + ((qrow0 + 16 + qr) * KVSTR + qk) * 2;
    unsigned kBase = ksb + (kRow * KVSTR + kK) * 2;
    unsigned vBase = vsb + (vRow * KVSTR + vD) * 2;

    CP_WAIT(1);
    __syncthreads();

    const int NKB = SEQLEN / 64;    // 32, even

    auto flash_step = [&](int kb, unsigned soff) {
        int k0 = kb * 64;
        unsigned kbase = kBase + soff;
        unsigned vbase = vBase + soff;

        float sc[2][8][4];
        #pragma unroll
        for (int mt = 0; mt < 2; mt++)
            #pragma unroll
            for (int nt = 0; nt < 8; nt++)
                #pragma unroll
                for (int i = 0; i < 4; i++) sc[mt][nt][i] = 0.f;
        #pragma unroll
        for (int ks = 0; ks < 8; ks++) {
            unsigned qa0[4], qa1[4];
            LDSM4(qa0, qBase0 + ks * 32);
            LDSM4(qa1, qBase1 + ks * 32);
            #pragma unroll
            for (int p = 0; p < 4; p++) {
                unsigned bb[4];
                LDSM4(bb, kbase + p * 16 * KVSTR * 2 + ks * 32);
                mma16(sc[0][2*p],   qa0, bb[0], bb[1]);
                mma16(sc[0][2*p+1], qa0, bb[2], bb[3]);
                mma16(sc[1][2*p],   qa1, bb[0], bb[1]);
                mma16(sc[1][2*p+1], qa1, bb[2], bb[3]);
            }
        }

        unsigned ph[2][16];
        #pragma unroll
        for (int nt = 0; nt < 8; nt++) {
            float2 bb = *(float2*)&Bias[k0 + nt * 8 + 2 * t];
            #pragma unroll
            for (int mt = 0; mt < 2; mt++) {
                float p0 = ex2f(fmaf(sc[mt][nt][0], SCL2, bb.x));
                float p1 = ex2f(fmaf(sc[mt][nt][1], SCL2, bb.y));
                float p2 = ex2f(fmaf(sc[mt][nt][2], SCL2, bb.x));
                float p3 = ex2f(fmaf(sc[mt][nt][3], SCL2, bb.y));
                ph[mt][nt * 2]     = packh2(p0, p1);
                ph[mt][nt * 2 + 1] = packh2(p2, p3);
            }
        }

        #pragma unroll
        for (int j = 0; j < 4; j++) {
            unsigned pa0[4], pa1[4];
            pa0[0] = ph[0][4*j];   pa0[1] = ph[0][4*j+1];
            pa0[2] = ph[0][4*j+2]; pa0[3] = ph[0][4*j+3];
            pa1[0] = ph[1][4*j];   pa1[1] = ph[1][4*j+1];
            pa1[2] = ph[1][4*j+2]; pa1[3] = ph[1][4*j+3];
            mma16(lc[0], pa0, ONESH, ONESH);
            mma16(lc[1], pa1, ONESH, ONESH);
            unsigned vrow = vbase + j * 16 * KVSTR * 2;
            #pragma unroll
            for (int p = 0; p < 8; p++) {
                unsigned vb[4];
                LDSM4T(vb, vrow + p * 32);
                mma16(o[0][2*p],   pa0, vb[0], vb[1]);
                mma16(o[0][2*p+1], pa0, vb[2], vb[3]);
                mma16(o[1][2*p],   pa1, vb[0], vb[1]);
                mma16(o[1][2*p+1], pa1, vb[2], vb[3]);
            }
        }
    };

    for (int kb = 0; kb < NKB; kb += 2) {
        flash_step(kb, 0);
        __syncthreads();
        if (kb + 2 < NKB) issue_kv(kb + 2, 0); else CP_COMMIT();
        CP_WAIT(1);
        __syncthreads();

        flash_step(kb + 1, KVSTAGE);
        __syncthreads();
        if (kb + 3 < NKB) issue_kv(kb + 3, 1); else CP_COMMIT();
        CP_WAIT(1);
        __syncthreads();
    }

    #pragma unroll
    for (int mt = 0; mt < 2; mt++) {
        float i0 = 1.f / lc[mt][0];
        float i1 = 1.f / lc[mt][2];
        size_t r0 = (size_t)(b * SEQLEN + q0 + qrow0 + mt * 16 + g) * DIM;
        size_t r1 = r0 + 8 * DIM;
        #pragma unroll
        for (int nt = 0; nt < 16; nt++) {
            int col = h * HD + nt * 8 + 2 * t;
            *(__half2*)&Oh[r0 + col] = __floats2half2_rn(o[mt][nt][0] * i0, o[mt][nt][1] * i0);
            *(__half2*)&Oh[r1 + col] = __floats2half2_rn(o[mt][nt][2] * i1, o[mt][nt][3] * i1);
        }
    }
}

// ---------------- launch ----------------
extern "C" void kernel_launch(void* const* d_in, const int* in_sizes, int n_in,
                              void* d_out, int out_size) {
    const float* x     = (const float*)d_in[0];
    const int*   mask  = (const int*)  d_in[1];
    const float* fc    = (const float*)d_in[2];
    const float* fs    = (const float*)d_in[3];
    const float* qkv_w = (const float*)d_in[4];
    const float* out_w = (const float*)d_in[5];
    const float* s_q   = (const float*)d_in[6];
    const float* s_k   = (const float*)d_in[7];
    float* out = (float*)d_out;

    void *p1, *p2, *p3, *p4, *p5, *p6, *p7;
    cudaGetSymbolAddress(&p1, g_xh);
    cudaGetSymbolAddress(&p2, g_wqh);
    cudaGetSymbolAddress(&p3, g_woh);
    cudaGetSymbolAddress(&p4, g_qh);
    cudaGetSymbolAddress(&p5, g_kh);
    cudaGetSymbolAddress(&p6, g_vh);
    cudaGetSymbolAddress(&p7, g_attnh);
    __half* xh    = (__half*)p1;
    __half* wqh   = (__half*)p2;
    __half* woh   = (__half*)p3;
    __half* qh    = (__half*)p4;
    __half* kh    = (__half*)p5;
    __half* vh    = (__half*)p6;
    __half* attnh = (__half*)p7;

    cudaFuncSetAttribute(gemm_qkv,  cudaFuncAttributeMaxDynamicSharedMemorySize, GEMM_SMEM);
    cudaFuncSetAttribute(gemm_fp16, cudaFuncAttributeMaxDynamicSharedMemorySize, GEMM_SMEM);
    cudaFuncSetAttribute(flash_fp16, cudaFuncAttributeMaxDynamicSharedMemorySize, FSMEM);

    prep_kernel<<<4096 + QKV_OUT + DIM, 256>>>(x, xh, qkv_w, wqh, out_w, woh);

    gemm_qkv<<<dim3(QKV_OUT / 128, TOKENS / 128), 256, GEMM_SMEM>>>(
        xh, wqh, fc, fs, s_q, s_k, qh, kh, vh);

    flash_fp16<<<dim3(SEQLEN / 128, NH, BSZ), 128, FSMEM>>>(qh, kh, vh, mask, attnh);

    gemm_fp16<<<dim3(DIM / 128, TOKENS / 128), 256, GEMM_SMEM>>>(
        attnh, woh, out, TOKENS, DIM, DIM);
}

// round 16
// speedup vs baseline: 1.0373x; 1.0373x over previous
#include <cuda_runtime.h>
#include <cuda_fp16.h>
#include <math.h>
#include <cstdint>

// ---------------- problem constants ----------------
#define BSZ     2
#define SEQLEN  2048
#define DIM     2048
#define NH      16
#define NKV     4
#define HD      128
#define QKV_OUT 3072
#define TOKENS  (BSZ*SEQLEN)
#define REPARAM_EPS 1e-6f
#define L2_EPS      1e-12f

// ---------------- device scratch ----------------
__device__ __half g_xh   [TOKENS * DIM];
__device__ __half g_wqh  [QKV_OUT * DIM];
__device__ __half g_woh  [DIM * DIM];
__device__ __half g_qh   [TOKENS * NH  * HD];
__device__ __half g_kh   [TOKENS * NKV * HD];
__device__ __half g_vh   [TOKENS * NKV * HD];
__device__ __half g_attnh[TOKENS * DIM];

// ---------------- helpers ----------------
__device__ __forceinline__ void mma16(float* c, const unsigned* a, unsigned b0, unsigned b1) {
    asm volatile(
        "mma.sync.aligned.m16n8k16.row.col.f32.f16.f16.f32 "
        "{%0,%1,%2,%3},{%4,%5,%6,%7},{%8,%9},{%0,%1,%2,%3};"
        : "+f"(c[0]), "+f"(c[1]), "+f"(c[2]), "+f"(c[3])
        : "r"(a[0]), "r"(a[1]), "r"(a[2]), "r"(a[3]), "r"(b0), "r"(b1));
}
__device__ __forceinline__ unsigned smem_u32(const void* p) {
    return (unsigned)__cvta_generic_to_shared(p);
}
__device__ __forceinline__ void cp16(unsigned dst, const void* src) {
    asm volatile("cp.async.cg.shared.global [%0], [%1], 16;" :: "r"(dst), "l"(src));
}
#define CP_COMMIT() asm volatile("cp.async.commit_group;")
#define CP_WAIT(n)  asm volatile("cp.async.wait_group %0;" :: "n"(n))
#define LDSM4(r, addr) \
    asm volatile("ldmatrix.sync.aligned.m8n8.x4.shared.b16 {%0,%1,%2,%3},[%4];" \
        : "=r"((r)[0]), "=r"((r)[1]), "=r"((r)[2]), "=r"((r)[3]) : "r"(addr))
#define LDSM4T(r, addr) \
    asm volatile("ldmatrix.sync.aligned.m8n8.x4.trans.shared.b16 {%0,%1,%2,%3},[%4];" \
        : "=r"((r)[0]), "=r"((r)[1]), "=r"((r)[2]), "=r"((r)[3]) : "r"(addr))
__device__ __forceinline__ unsigned packh2(float x, float y) {
    __half2 h = __floats2half2_rn(x, y);
    return *(unsigned*)&h;
}
__device__ __forceinline__ float ex2f(float x) {
    float r;
    asm("ex2.approx.ftz.f32 %0, %1;" : "=f"(r) : "f"(x));
    return r;
}

// ---------------- combined prep: f2h(x) + rownorm(qkv_w) + rownorm(out_w) ---
// ONE-PASS wnorm: the 8 floats/thread stay in registers across the reduction.
__device__ __forceinline__ void wnorm_row(const float* __restrict__ row,
                                          __half* __restrict__ orow) {
    int c = threadIdx.x * 8;
    float4 v0 = *(const float4*)(row + c);
    float4 v1 = *(const float4*)(row + c + 4);
    float ss = v0.x*v0.x + v0.y*v0.y + v0.z*v0.z + v0.w*v0.w
             + v1.x*v1.x + v1.y*v1.y + v1.z*v1.z + v1.w*v1.w;
    #pragma unroll
    for (int off = 16; off; off >>= 1) ss += __shfl_xor_sync(0xffffffffu, ss, off);
    __shared__ float sp[8];
    if ((threadIdx.x & 31) == 0) sp[threadIdx.x >> 5] = ss;
    __syncthreads();
    __shared__ float s_inv;
    if (threadIdx.x == 0) {
        float tot = 0.f;
        #pragma unroll
        for (int i = 0; i < 8; i++) tot += sp[i];
        s_inv = 1.f / (sqrtf(tot) + REPARAM_EPS);
    }
    __syncthreads();
    float inv = s_inv;
    uint4 u;
    u.x = packh2(v0.x * inv, v0.y * inv);
    u.y = packh2(v0.z * inv, v0.w * inv);
    u.z = packh2(v1.x * inv, v1.y * inv);
    u.w = packh2(v1.z * inv, v1.w * inv);
    *(uint4*)&orow[c] = u;
}

__global__ void prep_kernel(const float* __restrict__ x, __half* __restrict__ xh,
                            const float* __restrict__ qkv_w, __half* __restrict__ wqh,
                            const float* __restrict__ out_w, __half* __restrict__ woh) {
    int bid = blockIdx.x;
    if (bid < 4096) {
        int i = (bid * 256 + threadIdx.x) * 8;
        float4 a = *(const float4*)(x + i);
        float4 b = *(const float4*)(x + i + 4);
        uint4 u;
        u.x = packh2(a.x, a.y); u.y = packh2(a.z, a.w);
        u.z = packh2(b.x, b.y); u.w = packh2(b.z, b.w);
        *(uint4*)&xh[i] = u;
    } else if (bid < 4096 + QKV_OUT) {
        int r = bid - 4096;
        wnorm_row(qkv_w + (size_t)r * DIM, wqh + (size_t)r * DIM);
    } else {
        int r = bid - 4096 - QKV_OUT;
        wnorm_row(out_w + (size_t)r * DIM, woh + (size_t)r * DIM);
    }
}

// ---------------- shared GEMM mainloop config (3-stage dynamic ring) --------
#define GBK    64
#define GSTRH  72
#define GSTAGE (128 * GSTRH)
#define GEMM_SMEM (3 * 2 * GSTAGE * 2)

#define GEMM_MAINLOOP(A_, B_, K_)                                              \
    extern __shared__ char smraw[];                                            \
    __half* As = (__half*)smraw;                                               \
    __half* Bs = As + 3 * GSTAGE;                                              \
    unsigned asb = smem_u32(As), bsb = smem_u32(Bs);                           \
    int tid = threadIdx.x, lane = tid & 31, wid = tid >> 5;                    \
    int wm = wid & 3, wn = wid >> 2, g = lane >> 2, t = lane & 3;              \
    int bm = blockIdx.y * 128, bn = blockIdx.x * 128;                          \
    int aRow = wm * 32 + ((lane >> 3) & 1) * 8 + (lane & 7);                   \
    int aK   = ((lane >> 4) & 1) * 8;                                          \
    int bRow = wn * 64 + ((lane >> 4) & 1) * 8 + (lane & 7);                   \
    int bK   = ((lane >> 3) & 1) * 8;                                          \
    unsigned aBase = asb + (aRow * GSTRH + aK) * 2;                            \
    unsigned bBase = bsb + (bRow * GSTRH + bK) * 2;                            \
    const unsigned STAGE = GSTAGE * 2;                                         \
    float acc[2][8][4];                                                        \
    _Pragma("unroll")                                                          \
    for (int mt = 0; mt < 2; mt++)                                             \
        _Pragma("unroll")                                                      \
        for (int nt = 0; nt < 8; nt++)                                         \
            _Pragma("unroll")                                                  \
            for (int i = 0; i < 4; i++) acc[mt][nt][i] = 0.f;                  \
    auto issue = [&](int kb, int s) {                                          \
        int k0 = kb * GBK;                                                     \
        _Pragma("unroll")                                                      \
        for (int i = 0; i < 4; i++) {                                          \
            int idx = tid + i * 256;                                           \
            int r = idx >> 3, c = idx & 7;                                     \
            cp16(asb + (s * GSTAGE + r * GSTRH + c * 8) * 2,                   \
                 (A_) + (size_t)(bm + r) * (K_) + k0 + c * 8);                 \
            cp16(bsb + (s * GSTAGE + r * GSTRH + c * 8) * 2,                   \
                 (B_) + (size_t)(bn + r) * (K_) + k0 + c * 8);                 \
        }                                                                      \
        CP_COMMIT();                                                           \
    };                                                                         \
    int NIT = (K_) / GBK;                                                      \
    issue(0, 0);                                                               \
    issue(1, 1);                                                               \
    int srd = 0, swr = 2;                                                      \
    for (int kb = 0; kb < NIT; kb++) {                                         \
        CP_WAIT(1);                                                            \
        __syncthreads();                                                       \
        if (kb + 2 < NIT) issue(kb + 2, swr); else CP_COMMIT();                \
        unsigned aoff = aBase + srd * STAGE;                                   \
        unsigned boff = bBase + srd * STAGE;                                   \
        _Pragma("unroll")                                                      \
        for (int ks = 0; ks < 4; ks++) {                                       \
            unsigned a0[4], a1[4];                                             \
            LDSM4(a0, aoff + ks * 32);                                         \
            LDSM4(a1, aoff + ks * 32 + 16 * GSTRH * 2);                        \
            _Pragma("unroll")                                                  \
            for (int p = 0; p < 4; p++) {                                      \
                unsigned bb[4];                                                \
                LDSM4(bb, boff + ks * 32 + p * 16 * GSTRH * 2);                \
                mma16(acc[0][2*p],   a0, bb[0], bb[1]);                        \
                mma16(acc[0][2*p+1], a0, bb[2], bb[3]);                        \
                mma16(acc[1][2*p],   a1, bb[0], bb[1]);                        \
                mma16(acc[1][2*p+1], a1, bb[2], bb[3]);                        \
            }                                                                  \
        }                                                                      \
        srd = (srd == 2) ? 0 : srd + 1;                                        \
        swr = (swr == 2) ? 0 : swr + 1;                                        \
    }

// ---------------- GEMM1: QKV projection with FUSED rope/l2norm epilogue -----
__global__ __launch_bounds__(256, 2) void gemm_qkv(const __half* __restrict__ A,
                                                   const __half* __restrict__ B,
                                                   const float* __restrict__ fc,
                                                   const float* __restrict__ fs,
                                                   const float* __restrict__ s_q,
                                                   const float* __restrict__ s_k,
                                                   __half* __restrict__ qo,
                                                   __half* __restrict__ ko,
                                                   __half* __restrict__ vo) {
    GEMM_MAINLOOP(A, B, DIM)

    int h = blockIdx.x;
    int row0 = bm + wm * 32 + g;

    if (h >= 20) {
        __half* dst = vo + (h - 20) * HD;
        #pragma unroll
        for (int mt = 0; mt < 2; mt++) {
            size_t r0 = (size_t)(row0 + mt * 16) * (NKV * HD);
            size_t r1 = r0 + (size_t)8 * (NKV * HD);
            #pragma unroll
            for (int nt = 0; nt < 8; nt++) {
                int d = wn * 64 + nt * 8 + 2 * t;
                *(__half2*)&dst[r0 + d] = __floats2half2_rn(acc[mt][nt][0], acc[mt][nt][1]);
                *(__half2*)&dst[r1 + d] = __floats2half2_rn(acc[mt][nt][2], acc[mt][nt][3]);
            }
        }
        return;
    }

    __syncthreads();
    float* ssred = (float*)smraw;          // [2][128]

    float ss[2][2] = {{0.f, 0.f}, {0.f, 0.f}};
    #pragma unroll
    for (int mt = 0; mt < 2; mt++) {
        int s0 = (row0 + mt * 16) & (SEQLEN - 1);
        int s1 = (row0 + mt * 16 + 8) & (SEQLEN - 1);
        #pragma unroll
        for (int nt = 0; nt < 8; nt++) {
            int i = wn * 32 + nt * 4 + t;
            float c0 = fc[s0 * 64 + i], sn0 = fs[s0 * 64 + i];
            float c1 = fc[s1 * 64 + i], sn1 = fs[s1 * 64 + i];
            float xr0 = acc[mt][nt][0], xi0 = acc[mt][nt][1];
            float xr1 = acc[mt][nt][2], xi1 = acc[mt][nt][3];
            float or0 = xr0 * c0 - xi0 * sn0, oi0 = xr0 * sn0 + xi0 * c0;
            float or1 = xr1 * c1 - xi1 * sn1, oi1 = xr1 * sn1 + xi1 * c1;
            acc[mt][nt][0] = or0; acc[mt][nt][1] = oi0;
            acc[mt][nt][2] = or1; acc[mt][nt][3] = oi1;
            ss[mt][0] += or0 * or0 + oi0 * oi0;
            ss[mt][1] += or1 * or1 + oi1 * oi1;
        }
        ss[mt][0] += __shfl_xor_sync(0xffffffffu, ss[mt][0], 1);
        ss[mt][0] += __shfl_xor_sync(0xffffffffu, ss[mt][0], 2);
        ss[mt][1] += __shfl_xor_sync(0xffffffffu, ss[mt][1], 1);
        ss[mt][1] += __shfl_xor_sync(0xffffffffu, ss[mt][1], 2);
    }
    int lr0 = wm * 32 + g;
    if (t == 0) {
        ssred[wn * 128 + lr0]      = ss[0][0];
        ssred[wn * 128 + lr0 + 8]  = ss[0][1];
        ssred[wn * 128 + lr0 + 16] = ss[1][0];
        ssred[wn * 128 + lr0 + 24] = ss[1][1];
    }
    __syncthreads();

    const float* sc = (h < NH) ? s_q : s_k;
    __half* dst = (h < NH) ? (qo + h * HD) : (ko + (h - NH) * HD);
    int ldo = (h < NH) ? (NH * HD) : (NKV * HD);

    #pragma unroll
    for (int mt = 0; mt < 2; mt++) {
        float inv0 = 1.f / (sqrtf(ssred[lr0 + mt*16]     + ssred[128 + lr0 + mt*16])     + L2_EPS);
        float inv1 = 1.f / (sqrtf(ssred[lr0 + mt*16 + 8] + ssred[128 + lr0 + mt*16 + 8]) + L2_EPS);
        size_t r0 = (size_t)(row0 + mt * 16) * ldo;
        size_t r1 = r0 + (size_t)8 * ldo;
        #pragma unroll
        for (int nt = 0; nt < 8; nt++) {
            int d = wn * 64 + nt * 8 + 2 * t;
            float2 scv = *(const float2*)&sc[d];
            *(__half2*)&dst[r0 + d] = __floats2half2_rn(acc[mt][nt][0] * inv0 * scv.x,
                                                        acc[mt][nt][1] * inv0 * scv.y);
            *(__half2*)&dst[r1 + d] = __floats2half2_rn(acc[mt][nt][2] * inv1 * scv.x,
                                                        acc[mt][nt][3] * inv1 * scv.y);
        }
    }
}

// ---------------- GEMM2: out projection (fp32 output) ----------------------
__global__ __launch_bounds__(256, 2) void gemm_fp16(const __half* __restrict__ A,
                                                    const __half* __restrict__ B,
                                                    float* __restrict__ C,
                                                    int M, int N, int K) {
    GEMM_MAINLOOP(A, B, K)
    #pragma unroll
    for (int mt = 0; mt < 2; mt++) {
        int r0 = bm + wm * 32 + mt * 16 + g;
        #pragma unroll
        for (int nt = 0; nt < 8; nt++) {
            int c = bn + wn * 64 + nt * 8 + 2 * t;
            *(float2*)&C[(size_t)r0 * N + c]       = make_float2(acc[mt][nt][0], acc[mt][nt][1]);
            *(float2*)&C[(size_t)(r0 + 8) * N + c] = make_float2(acc[mt][nt][2], acc[mt][nt][3]);
        }
    }
}

// ---------------- flash attention: 4 warps x 32 q-rows, static-max ----------
// l on tensor cores (ones-column). Bias row precomputed to smem.
#define KVSTR 136
#define KVST  (64 * KVSTR)
#define FSMEM (((128 * KVSTR + 2 * 2 * KVST) * 2) + SEQLEN * 4)  // 112640 bytes
#define SCL2  16.322447f     // sqrt(128)*log2(e)
#define MAX2  8.0f
#define ONESH 0x3C003C00u    // half2(1,1)

__global__ __launch_bounds__(128, 2) void flash_fp16(const __half* __restrict__ Qh,
                                                     const __half* __restrict__ Kh,
                                                     const __half* __restrict__ Vh,
                                                     const int* __restrict__ mask,
                                                     __half* __restrict__ Oh) {
    extern __shared__ char smraw[];
    __half* Qs  = (__half*)smraw;
    __half* Ksm = Qs + 128 * KVSTR;
    __half* Vsm = Ksm + 2 * KVST;
    float* Bias = (float*)(Vsm + 2 * KVST);      // [SEQLEN]
    unsigned qsb = smem_u32(Qs), ksb = smem_u32(Ksm), vsb = smem_u32(Vsm);

    int tid = threadIdx.x, lane = tid & 31, wid = tid >> 5;
    int g = lane >> 2, t = lane & 3;
    int qb = blockIdx.x, h = blockIdx.y, b = blockIdx.z, hk = h >> 2;
    int q0 = qb * 128, qrow0 = wid * 32;
    const unsigned KVSTAGE = KVST * 2;

    auto issue_kv = [&](int kb, int s) {
        int k0 = kb * 64;
        #pragma unroll
        for (int i = 0; i < 8; i++) {
            int idx = tid + i * 128;
            int r = idx >> 4, c = idx & 15;
            size_t tok = (size_t)(b * SEQLEN + k0 + r);
            cp16(ksb + s * KVSTAGE + (r * KVSTR + c * 8) * 2,
                 Kh + (tok * NKV + hk) * HD + c * 8);
            cp16(vsb + s * KVSTAGE + (r * KVSTR + c * 8) * 2,
                 Vh + (tok * NKV + hk) * HD + c * 8);
        }
        CP_COMMIT();
    };

    #pragma unroll
    for (int i = 0; i < 16; i++) {
        int idx = tid + i * 128;
        int r = idx >> 4, c = idx & 15;
        cp16(qsb + (r * KVSTR + c * 8) * 2,
             Qh + ((size_t)(b * SEQLEN + q0 + r) * NH + h) * HD + c * 8);
    }
    CP_COMMIT();
    issue_kv(0, 0);
    issue_kv(1, 1);

    // precompute mask bias row (once per CTA)
    for (int i = tid; i < SEQLEN; i += 128)
        Bias[i] = mask[b * SEQLEN + i] ? -MAX2 : -1e30f;

    float o[2][16][4];
    #pragma unroll
    for (int mt = 0; mt < 2; mt++)
        #pragma unroll
        for (int nt = 0; nt < 16; nt++)
            #pragma unroll
            for (int i = 0; i < 4; i++) o[mt][nt][i] = 0.f;
    float lc[2][4];
    #pragma unroll
    for (int mt = 0; mt < 2; mt++)
        #pragma unroll
        for (int i = 0; i < 4; i++) lc[mt][i] = 0.f;

    int qr  = ((lane >> 3) & 1) * 8 + (lane & 7);
    int qk  = ((lane >> 4) & 1) * 8;
    int kRow = ((lane >> 4) & 1) * 8 + (lane & 7);
    int kK   = ((lane >> 3) & 1) * 8;
    int vRow = lane & 15;
    int vD   = ((lane >> 4) & 1) * 8;
    unsigned qBase0 = qsb + ((qrow0 + qr) * KVSTR + qk) * 2;
    unsigned qBase1 = qsb + ((qrow0 + 16 + qr) * KVSTR + qk) * 2;

    CP_WAIT(1);
    __syncthreads();

    const int NKB = SEQLEN / 64;
    for (int kb = 0; kb < NKB; kb++) {
        int k0 = kb * 64;
        int srd = kb & 1;
        unsigned kbase = ksb + srd * KVSTAGE + (kRow * KVSTR + kK) * 2;
        unsigned vbase = vsb + srd * KVSTAGE + (vRow * KVSTR + vD) * 2;

        float sc[2][8][4];
        #pragma unroll
        for (int mt = 0; mt < 2; mt++)
            #pragma unroll
            for (int nt = 0; nt < 8; nt++)
                #pragma unroll
                for (int i = 0; i < 4; i++) sc[mt][nt][i] = 0.f;
        #pragma unroll
        for (int ks = 0; ks < 8; ks++) {
            unsigned qa0[4], qa1[4];
            LDSM4(qa0, qBase0 + ks * 32);
            LDSM4(qa1, qBase1 + ks * 32);
            #pragma unroll
            for (int p = 0; p < 4; p++) {
                unsigned bb[4];
                LDSM4(bb, kbase + p * 16 * KVSTR * 2 + ks * 32);
                mma16(sc[0][2*p],   qa0, bb[0], bb[1]);
                mma16(sc[0][2*p+1], qa0, bb[2], bb[3]);
                mma16(sc[1][2*p],   qa1, bb[0], bb[1]);
                mma16(sc[1][2*p+1], qa1, bb[2], bb[3]);
            }
        }

        unsigned ph[2][16];
        #pragma unroll
        for (int nt = 0; nt < 8; nt++) {
            float2 bb = *(float2*)&Bias[k0 + nt * 8 + 2 * t];
            #pragma unroll
            for (int mt = 0; mt < 2; mt++) {
                float p0 = ex2f(fmaf(sc[mt][nt][0], SCL2, bb.x));
                float p1 = ex2f(fmaf(sc[mt][nt][1], SCL2, bb.y));
                float p2 = ex2f(fmaf(sc[mt][nt][2], SCL2, bb.x));
                float p3 = ex2f(fmaf(sc[mt][nt][3], SCL2, bb.y));
                ph[mt][nt * 2]     = packh2(p0, p1);
                ph[mt][nt * 2 + 1] = packh2(p2, p3);
            }
        }

        #pragma unroll
        for (int j = 0; j < 4; j++) {
            unsigned pa0[4], pa1[4];
            pa0[0] = ph[0][4*j];   pa0[1] = ph[0][4*j+1];
            pa0[2] = ph[0][4*j+2]; pa0[3] = ph[0][4*j+3];
            pa1[0] = ph[1][4*j];   pa1[1] = ph[1][4*j+1];
            pa1[2] = ph[1][4*j+2]; pa1[3] = ph[1][4*j+3];
            mma16(lc[0], pa0, ONESH, ONESH);
            mma16(lc[1], pa1, ONESH, ONESH);
            unsigned vrow = vbase + j * 16 * KVSTR * 2;
            #pragma unroll
            for (int p = 0; p < 8; p++) {
                unsigned vb[4];
                LDSM4T(vb, vrow + p * 32);
                mma16(o[0][2*p],   pa0, vb[0], vb[1]);
                mma16(o[0][2*p+1], pa0, vb[2], vb[3]);
                mma16(o[1][2*p],   pa1, vb[0], vb[1]);
                mma16(o[1][2*p+1], pa1, vb[2], vb[3]);
            }
        }

        __syncthreads();
        if (kb + 2 < NKB) issue_kv(kb + 2, srd); else CP_COMMIT();
        CP_WAIT(1);
        __syncthreads();
    }

    #pragma unroll
    for (int mt = 0; mt < 2; mt++) {
        float i0 = 1.f / lc[mt][0];
        float i1 = 1.f / lc[mt][2];
        size_t r0 = (size_t)(b * SEQLEN + q0 + qrow0 + mt * 16 + g) * DIM;
        size_t r1 = r0 + 8 * DIM;
        #pragma unroll
        for (int nt = 0; nt < 16; nt++) {
            int col = h * HD + nt * 8 + 2 * t;
            *(__half2*)&Oh[r0 + col] = __floats2half2_rn(o[mt][nt][0] * i0, o[mt][nt][1] * i0);
            *(__half2*)&Oh[r1 + col] = __floats2half2_rn(o[mt][nt][2] * i1, o[mt][nt][3] * i1);
        }
    }
}

// ---------------- launch ----------------
extern "C" void kernel_launch(void* const* d_in, const int* in_sizes, int n_in,
                              void* d_out, int out_size) {
    const float* x     = (const float*)d_in[0];
    const int*   mask  = (const int*)  d_in[1];
    const float* fc    = (const float*)d_in[2];
    const float* fs    = (const float*)d_in[3];
    const float* qkv_w = (const float*)d_in[4];
    const float* out_w = (const float*)d_in[5];
    const float* s_q   = (const float*)d_in[6];
    const float* s_k   = (const float*)d_in[7];
    float* out = (float*)d_out;

    void *p1, *p2, *p3, *p4, *p5, *p6, *p7;
    cudaGetSymbolAddress(&p1, g_xh);
    cudaGetSymbolAddress(&p2, g_wqh);
    cudaGetSymbolAddress(&p3, g_woh);
    cudaGetSymbolAddress(&p4, g_qh);
    cudaGetSymbolAddress(&p5, g_kh);
    cudaGetSymbolAddress(&p6, g_vh);
    cudaGetSymbolAddress(&p7, g_attnh);
    __half* xh    = (__half*)p1;
    __half* wqh   = (__half*)p2;
    __half* woh   = (__half*)p3;
    __half* qh    = (__half*)p4;
    __half* kh    = (__half*)p5;
    __half* vh    = (__half*)p6;
    __half* attnh = (__half*)p7;

    cudaFuncSetAttribute(gemm_qkv,  cudaFuncAttributeMaxDynamicSharedMemorySize, GEMM_SMEM);
    cudaFuncSetAttribute(gemm_fp16, cudaFuncAttributeMaxDynamicSharedMemorySize, GEMM_SMEM);
    cudaFuncSetAttribute(flash_fp16, cudaFuncAttributeMaxDynamicSharedMemorySize, FSMEM);

    prep_kernel<<<4096 + QKV_OUT + DIM, 256>>>(x, xh, qkv_w, wqh, out_w, woh);

    gemm_qkv<<<dim3(QKV_OUT / 128, TOKENS / 128), 256, GEMM_SMEM>>>(
        xh, wqh, fc, fs, s_q, s_k, qh, kh, vh);

    flash_fp16<<<dim3(SEQLEN / 128, NH, BSZ), 128, FSMEM>>>(qh, kh, vh, mask, attnh);

    gemm_fp16<<<dim3(DIM / 128, TOKENS / 128), 256, GEMM_SMEM>>>(
        attnh, woh, out, TOKENS, DIM, DIM);
}